// round 4
// baseline (speedup 1.0000x reference)
#include <cuda_runtime.h>
#include <cuda_fp16.h>
#include <cstdint>

// Problem constants
#define BB  32
#define TT  256
#define DD  512
#define MPP 20

constexpr int TM     = 128;            // CTA t rows
constexpr int TN     = 256;            // CTA s cols (full T)
constexpr int KC     = 32;             // k per pipeline stage (one k32 fp8 mma step)
constexpr int NST    = DD / KC;        // 16 stages of work
constexpr int STAGES = 4;              // cp.async ring depth
constexpr int ROWA   = 80;             // A row bytes: 32 f16 = 64B data + 16B pad
constexpr int ROWBB  = 48;             // B row bytes: 32 fp8 = 32B data + 16B pad
constexpr int A_BYTES   = TM * ROWA;              // 10240
constexpr int B_BYTES   = TN * ROWBB;             // 12288
constexpr int STG_BYTES = A_BYTES + B_BYTES;      // 22528

constexpr int S_KMS = 0;               // 512 halves = 1024 B
constexpr int S_RED = 2048;            // 128*4 floats = 2048 B
constexpr int S_BUF = 6144;            // 128B aligned
constexpr int S_TOTAL = S_BUF + STAGES * STG_BYTES;  // 96256 B

// scratch (static device arrays: allocation-free per harness rules)
__device__ __half  g_lt[BB * TT * DD];           // f16, natural order
__device__ uint8_t g_rt[BB * TT * DD];           // e4m3, k-pair interleaved per 16

static __device__ __forceinline__ uint32_t s2u(const void* p) {
    return (uint32_t)__cvta_generic_to_shared(p);
}

#define CP16(dst, src) \
    asm volatile("cp.async.cg.shared.global [%0], [%1], 16;" :: "r"(dst), "l"(src))

#define LDSM4(r0, r1, r2, r3, addr)                                              \
    asm volatile("ldmatrix.sync.aligned.m8n8.x4.shared.b16 {%0,%1,%2,%3}, [%4];" \
                 : "=r"(r0), "=r"(r1), "=r"(r2), "=r"(r3) : "r"(addr))

// fp8 e4m3 mma, f32 accumulate
#define MMAF8(d, a0, a1, a2, a3, b0, b1)                                          \
    asm volatile("mma.sync.aligned.m16n8k32.row.col.f32.e4m3.e4m3.f32 "           \
                 "{%0,%1,%2,%3},{%4,%5,%6,%7},{%8,%9},{%0,%1,%2,%3};"             \
                 : "+f"(d[0]), "+f"(d[1]), "+f"(d[2]), "+f"(d[3])                  \
                 : "r"(a0), "r"(a1), "r"(a2), "r"(a3), "r"(b0), "r"(b1))

static __device__ __forceinline__ uint32_t hmul2u(uint32_t a, uint32_t b) {
    __half2 r = __hmul2(*reinterpret_cast<__half2*>(&a),
                        *reinterpret_cast<__half2*>(&b));
    return *reinterpret_cast<uint32_t*>(&r);
}

// pack two f16x2->e4m3x2 conversions into one u32: bytes [lo(x).lo, lo(x).hi, lo(y).lo, lo(y).hi]
static __device__ __forceinline__ uint32_t cvt2u(uint32_t x, uint32_t y) {
    uint32_t r;
    asm("{\n\t.reg .b16 l, h;\n\t"
        "cvt.rn.satfinite.e4m3x2.f16x2 l, %1;\n\t"
        "cvt.rn.satfinite.e4m3x2.f16x2 h, %2;\n\t"
        "mov.b32 %0, {l, h};\n\t}"
        : "=r"(r) : "r"(x), "r"(y));
    return r;
}

// f32 pair -> e4m3x2 (lo byte = a, hi byte = b)
static __device__ __forceinline__ uint16_t cvt8pair(float a, float b) {
    uint16_t r;
    asm("cvt.rn.satfinite.e4m3x2.f32 %0, %1, %2;" : "=h"(r) : "f"(b), "f"(a));
    return r;
}

// ---------------------------------------------------------------------------
// Kernel 1: lt f32->f16 (natural); rt f32->e4m3 with per-16 k-pair interleave
// [p0,p4,p1,p5,p2,p6,p3,p7] so ldmatrix.b16 fragments match the in-reg A build.
// Each thread handles 16 consecutive k values of both tensors.
// ---------------------------------------------------------------------------
__global__ void cvt_kernel(const float* __restrict__ lt, const float* __restrict__ rt) {
    int i = blockIdx.x * blockDim.x + threadIdx.x;  // 16-elem unit index
    const float4* pl = reinterpret_cast<const float4*>(lt) + i * 4;
    const float4* pr = reinterpret_cast<const float4*>(rt) + i * 4;

    // lt: 16 f32 -> 16 f16, natural order
    {
        uint32_t w[8];
        float4 v;
#pragma unroll
        for (int j = 0; j < 4; j++) {
            v = pl[j];
            __half2 h0 = __floats2half2_rn(v.x, v.y);
            __half2 h1 = __floats2half2_rn(v.z, v.w);
            w[j * 2]     = *reinterpret_cast<uint32_t*>(&h0);
            w[j * 2 + 1] = *reinterpret_cast<uint32_t*>(&h1);
        }
        uint4* d = reinterpret_cast<uint4*>(g_lt + (size_t)i * 16);
        d[0] = make_uint4(w[0], w[1], w[2], w[3]);
        d[1] = make_uint4(w[4], w[5], w[6], w[7]);
    }
    // rt: 16 f32 -> 16 e4m3, pair-interleaved
    {
        float f[16];
        float4 v;
#pragma unroll
        for (int j = 0; j < 4; j++) {
            v = pr[j];
            f[j * 4] = v.x; f[j * 4 + 1] = v.y; f[j * 4 + 2] = v.z; f[j * 4 + 3] = v.w;
        }
        uint16_t c[8];
#pragma unroll
        for (int j = 0; j < 8; j++) c[j] = cvt8pair(f[2 * j], f[2 * j + 1]);
        uint4 o;
        o.x = (uint32_t)c[0] | ((uint32_t)c[4] << 16);
        o.y = (uint32_t)c[1] | ((uint32_t)c[5] << 16);
        o.z = (uint32_t)c[2] | ((uint32_t)c[6] << 16);
        o.w = (uint32_t)c[3] | ((uint32_t)c[7] << 16);
        *reinterpret_cast<uint4*>(g_rt + (size_t)i * 16) = o;
    }
}

// ---------------------------------------------------------------------------
// Kernel 2: one CTA = (b, t-tile 128, single m). scores = (lt .* km) @ rt^T
// via fp8 e4m3 mma.m16n8k32 (f32 acc). A: f16 in SMEM, km-scaled + cvt'd to
// fp8 in registers. B: fp8 in SMEM (pre-interleaved), ldmatrix.b16 direct.
// 16 warps 4(t) x 4(s); warp tile 32t x 64s. 4-stage cp.async pipeline.
// ---------------------------------------------------------------------------
__global__ __launch_bounds__(512, 1)
void match_kernel(const float* __restrict__ kw, float* __restrict__ out) {
    extern __shared__ __align__(128) char smem[];
    const int tid = threadIdx.x;
    const int b   = blockIdx.z;
    const int m   = blockIdx.y;
    const int t0  = blockIdx.x * TM;
    const uint32_t sbase = s2u(smem);
    const uint32_t sbuf  = sbase + S_BUF;

    // stage km row m as fp16
    __half* kms = reinterpret_cast<__half*>(smem + S_KMS);
    if (tid < DD) kms[tid] = __float2half_rn(kw[m * DD + tid]);

    const __half*  ltb = g_lt + (size_t)(b * TT + t0) * DD;
    const uint8_t* rtb = g_rt + (size_t)b * TT * DD;

    const int wid  = tid >> 5;
    const int lane = tid & 31;
    const int wt   = wid >> 2;   // t sub-tile (32 rows)
    const int ws   = wid & 3;    // s sub-tile (64 cols)

    const uint32_t aoff = (uint32_t)(wt * 32 + (lane & 15)) * ROWA + (lane >> 4) * 16;
    const uint32_t boff = (uint32_t)(ws * 64 + (lane & 7) + ((lane >> 4) << 3)) * ROWBB
                        + ((lane >> 3) & 1) * 16;
    const int c0 = (lane & 3) * 2;   // k base of this thread's A frag columns

    float acc[2][8][4];              // [t-frag][n-frag][reg] f32
#pragma unroll
    for (int ti = 0; ti < 2; ti++)
#pragma unroll
        for (int ni = 0; ni < 8; ni++)
#pragma unroll
            for (int r = 0; r < 4; r++) acc[ti][ni][r] = 0.0f;

    auto issue = [&](int st) {
        const uint32_t sb = sbuf + (st % STAGES) * STG_BYTES;
        {   // A: 512 chunks of 16B (f16 k32 per row = 64B = 4 chunks x 128 rows)
            int row = tid >> 2, sub = tid & 3;
            CP16(sb + row * ROWA + sub * 16, ltb + row * DD + st * KC + sub * 8);
        }
        {   // B: 512 chunks of 16B (fp8 k32 per row = 32B = 2 chunks x 256 rows)
            int row = tid >> 1, sub = tid & 1;
            CP16(sb + A_BYTES + row * ROWBB + sub * 16, rtb + row * DD + st * KC + sub * 16);
        }
    };

    auto compute = [&](int st) {
        const uint32_t sb = sbuf + (st % STAGES) * STG_BYTES;
        const int kb = st * KC;
        // B fragments: 4 ldsm.x4 over fp8-as-b16; r0/r1 = (b0,b1) of even ni,
        // r2/r3 = odd ni (same mapping validated in f16 kernels).
        uint32_t bfr[8][2];
#pragma unroll
        for (int nj = 0; nj < 4; nj++) {
            uint32_t r0, r1, r2, r3;
            LDSM4(r0, r1, r2, r3, sb + A_BYTES + boff + nj * (16 * ROWBB));
            bfr[nj * 2][0] = r0;     bfr[nj * 2][1] = r1;
            bfr[nj * 2 + 1][0] = r2; bfr[nj * 2 + 1][1] = r3;
        }
        // km scale pairs for this thread's k columns
        const uint32_t kp0 = *reinterpret_cast<const uint32_t*>(&kms[kb + c0]);
        const uint32_t kp1 = *reinterpret_cast<const uint32_t*>(&kms[kb + c0 + 8]);
        const uint32_t kp2 = *reinterpret_cast<const uint32_t*>(&kms[kb + c0 + 16]);
        const uint32_t kp3 = *reinterpret_cast<const uint32_t*>(&kms[kb + c0 + 24]);
#pragma unroll
        for (int ti = 0; ti < 2; ti++) {
            uint32_t h[8];
            LDSM4(h[0], h[1], h[2], h[3], sb + aoff + ti * (16 * ROWA));       // k 0..15
            LDSM4(h[4], h[5], h[6], h[7], sb + aoff + ti * (16 * ROWA) + 32);  // k 16..31
            // scale by km (h0/h1: k{2q,2q+1}; h2/h3: k{8+2q}; h4..h7: +16)
            uint32_t s0 = hmul2u(h[0], kp0), s1 = hmul2u(h[1], kp0);
            uint32_t s2 = hmul2u(h[2], kp1), s3 = hmul2u(h[3], kp1);
            uint32_t s4 = hmul2u(h[4], kp2), s5 = hmul2u(h[5], kp2);
            uint32_t s6 = hmul2u(h[6], kp3), s7 = hmul2u(h[7], kp3);
            // build fp8 A regs: byte slots [2q,2q+1,8+2q,8+2q+1] per 16-k half,
            // matching the interleaved B storage.
            uint32_t a0 = cvt2u(s0, s2);   // row g,   k-lo half
            uint32_t a1 = cvt2u(s1, s3);   // row g+8, k-lo half
            uint32_t a2 = cvt2u(s4, s6);   // row g,   k-hi half
            uint32_t a3 = cvt2u(s5, s7);   // row g+8, k-hi half
#pragma unroll
            for (int ni = 0; ni < 8; ni++)
                MMAF8(acc[ti][ni], a0, a1, a2, a3, bfr[ni][0], bfr[ni][1]);
        }
    };

    // Prologue: 3 stages in flight
    issue(0); asm volatile("cp.async.commit_group;" ::: "memory");
    issue(1); asm volatile("cp.async.commit_group;" ::: "memory");
    issue(2); asm volatile("cp.async.commit_group;" ::: "memory");

    for (int ki = 0; ki < NST; ki++) {
        asm volatile("cp.async.wait_group 2;" ::: "memory");
        __syncthreads();
        compute(ki);
        if (ki + 3 < NST) issue(ki + 3);
        asm volatile("cp.async.commit_group;" ::: "memory");
    }

    // Epilogue: max over s, tanh, store
    float* red = reinterpret_cast<float*>(smem + S_RED);
    __syncthreads();
#pragma unroll
    for (int ti = 0; ti < 2; ti++)
#pragma unroll
        for (int h = 0; h < 2; h++) {    // h=0: row g (d0,d1); h=1: row g+8 (d2,d3)
            float fm = -3.4e38f;
#pragma unroll
            for (int ni = 0; ni < 8; ni++)
                fm = fmaxf(fm, fmaxf(acc[ti][ni][h * 2], acc[ti][ni][h * 2 + 1]));
            fm = fmaxf(fm, __shfl_xor_sync(0xffffffffu, fm, 1));
            fm = fmaxf(fm, __shfl_xor_sync(0xffffffffu, fm, 2));
            if ((lane & 3) == 0) {
                int row = wt * 32 + ti * 16 + h * 8 + (lane >> 2);
                red[row * 4 + ws] = fm;
            }
        }
    __syncthreads();
    if (tid < TM) {
        const float* r = &red[tid * 4];
        float v = fmaxf(fmaxf(r[0], r[1]), fmaxf(r[2], r[3]));
        out[(size_t)(b * TT + t0 + tid) * MPP + m] = tanhf(v);
    }
}

// ---------------------------------------------------------------------------
// Launch: inputs: reps_lt[B,T,D] f32, reps_rt[B,T,D] f32, kernel[1,1,1,MP,D] f32.
// Output [B,T,MP] f32.
// ---------------------------------------------------------------------------
extern "C" void kernel_launch(void* const* d_in, const int* in_sizes, int n_in,
                              void* d_out, int out_size) {
    const float* lt = (const float*)d_in[0];
    const float* rt = (const float*)d_in[1];
    const float* kw = (const float*)d_in[2];
    float* out = (float*)d_out;

    const int n16 = (BB * TT * DD) / 16;  // 262,144 16-elem units
    cvt_kernel<<<n16 / 256, 256>>>(lt, rt);

    cudaFuncSetAttribute(match_kernel,
                         cudaFuncAttributeMaxDynamicSharedMemorySize, S_TOTAL);
    dim3 grid(TT / TM, MPP, BB);  // (2, 20, 32) = 1280 CTAs
    match_kernel<<<grid, 512, S_TOTAL>>>(kw, out);
}

// round 5
// speedup vs baseline: 1.5246x; 1.5246x over previous
#include <cuda_runtime.h>
#include <cuda_fp16.h>
#include <cstdint>

// Problem constants
#define BB  32
#define TT  256
#define DD  512
#define MPP 20

constexpr int TM     = 128;            // CTA t rows
constexpr int TN     = 128;            // CTA s cols (half of T)
constexpr int KC     = 32;             // k per pipeline stage
constexpr int NST    = DD / KC;        // 16 stages
constexpr int STAGES = 4;              // cp.async ring depth
constexpr int ROWB   = 80;             // padded smem row bytes (64B data + 16B pad)
constexpr int A_BYTES   = TM * ROWB;              // 10240
constexpr int B_BYTES   = TN * ROWB;              // 10240
constexpr int STG_BYTES = A_BYTES + B_BYTES;      // 20480

constexpr int S_KMS = 0;               // 2*512 halves = 2048 B
constexpr int S_RED = 2048;            // 2*128*2 floats = 2048 B
constexpr int S_BUF = 4096;            // 128B aligned
constexpr int S_TOTAL = S_BUF + STAGES * STG_BYTES;  // 86016 B

// static device scratch (allocation-free per harness rules)
__device__ __half g_lt[BB * TT * DD];
__device__ __half g_rt[BB * TT * DD];
__device__ float  g_red[2][BB * TT * MPP];   // per-s-half pre-tanh maxima

static __device__ __forceinline__ uint32_t s2u(const void* p) {
    return (uint32_t)__cvta_generic_to_shared(p);
}

#define CP16(dst, src) \
    asm volatile("cp.async.cg.shared.global [%0], [%1], 16;" :: "r"(dst), "l"(src))

#define LDSM4(r0, r1, r2, r3, addr)                                              \
    asm volatile("ldmatrix.sync.aligned.m8n8.x4.shared.b16 {%0,%1,%2,%3}, [%4];" \
                 : "=r"(r0), "=r"(r1), "=r"(r2), "=r"(r3) : "r"(addr))

#define MMA16816(d0, d1, a0, a1, a2, a3, b0, b1)                                  \
    asm volatile("mma.sync.aligned.m16n8k16.row.col.f16.f16.f16.f16 "             \
                 "{%0,%1},{%2,%3,%4,%5},{%6,%7},{%0,%1};"                         \
                 : "+r"(d0), "+r"(d1)                                             \
                 : "r"(a0), "r"(a1), "r"(a2), "r"(a3), "r"(b0), "r"(b1))

static __device__ __forceinline__ uint32_t hmul2u(uint32_t a, uint32_t b) {
    __half2 r = __hmul2(*reinterpret_cast<__half2*>(&a),
                        *reinterpret_cast<__half2*>(&b));
    return *reinterpret_cast<uint32_t*>(&r);
}

// ---------------------------------------------------------------------------
// Kernel 1: fp32 -> fp16 conversion of lt and rt
// ---------------------------------------------------------------------------
__global__ void cvt_kernel(const float* __restrict__ lt, const float* __restrict__ rt) {
    int i = blockIdx.x * blockDim.x + threadIdx.x;  // over n/4 float4 units
    float4 a = reinterpret_cast<const float4*>(lt)[i];
    float4 b = reinterpret_cast<const float4*>(rt)[i];
    __half2* dl = reinterpret_cast<__half2*>(g_lt);
    __half2* dr = reinterpret_cast<__half2*>(g_rt);
    dl[2*i]   = __floats2half2_rn(a.x, a.y);
    dl[2*i+1] = __floats2half2_rn(a.z, a.w);
    dr[2*i]   = __floats2half2_rn(b.x, b.y);
    dr[2*i+1] = __floats2half2_rn(b.z, b.w);
}

// ---------------------------------------------------------------------------
// Kernel 2: one CTA = (b, t-tile 128, s-half 128, m-pair).
// fp16 HMMA fp16-acc; raw lt fragments km-scaled in regs, B frags reused
// across both m. 8 warps 4(t) x 2(s); warp tile 32t x 64s x 2m.
// 256 threads, 2 CTAs/SM. Writes per-half max to g_red.
// ---------------------------------------------------------------------------
__global__ __launch_bounds__(256, 2)
void match_kernel(const float* __restrict__ kw) {
    extern __shared__ __align__(128) char smem[];
    const int tid = threadIdx.x;
    const int b   = blockIdx.z;
    const int m0  = blockIdx.y * 2;
    const int t0  = (blockIdx.x >> 1) * TM;
    const int sh  = blockIdx.x & 1;          // s-half
    const int s0  = sh * TN;
    const uint32_t sbase = s2u(smem);
    const uint32_t sbuf  = sbase + S_BUF;

    // stage km rows (m0, m0+1) as fp16
    __half* kms = reinterpret_cast<__half*>(smem + S_KMS);
#pragma unroll
    for (int e = tid; e < 2 * DD; e += 256) {
        int mi = e >> 9, c = e & (DD - 1);
        kms[e] = __float2half_rn(kw[(m0 + mi) * DD + c]);
    }

    const __half* ltb = g_lt + (size_t)(b * TT + t0) * DD;
    const __half* rtb = g_rt + (size_t)(b * TT + s0) * DD;

    const int wid  = tid >> 5;
    const int lane = tid & 31;
    const int wt   = wid >> 1;   // 0..3 : t sub-tile (32 rows)
    const int ws   = wid & 1;    // 0..1 : s sub-tile (64 cols)

    const uint32_t aoff = (uint32_t)(wt * 32 + (lane & 15)) * ROWB + (lane >> 4) * 16;
    const uint32_t boff = (uint32_t)(ws * 64 + (lane & 7) + ((lane >> 4) << 3)) * ROWB
                        + ((lane >> 3) & 1) * 16;
    const int c0 = (lane & 3) * 2;   // k column base of this thread's A frag elems

    uint32_t acc[2][2][8][2];        // [m][t-frag][n-frag][reg] fp16x2
#pragma unroll
    for (int mi = 0; mi < 2; mi++)
#pragma unroll
        for (int ti = 0; ti < 2; ti++)
#pragma unroll
            for (int ni = 0; ni < 8; ni++) {
                acc[mi][ti][ni][0] = 0u; acc[mi][ti][ni][1] = 0u;
            }

    auto issue = [&](int st) {
        const uint32_t sb = sbuf + (st % STAGES) * STG_BYTES;
        const int k0 = st * KC;
#pragma unroll
        for (int i = 0; i < 4; i++) {
            int c = tid + i * 256;   // 0..1023 : 512 A chunks then 512 B chunks
            if (c < 512) {
                int row = c >> 2, sub = c & 3;
                CP16(sb + row * ROWB + sub * 16, ltb + row * DD + k0 + sub * 8);
            } else {
                int c2 = c - 512, row = c2 >> 2, sub = c2 & 3;
                CP16(sb + A_BYTES + row * ROWB + sub * 16, rtb + row * DD + k0 + sub * 8);
            }
        }
    };

    auto compute = [&](int st) {
        const uint32_t sb = sbuf + (st % STAGES) * STG_BYTES;
#pragma unroll
        for (int kk = 0; kk < 2; kk++) {
            const int kb = st * KC + kk * 16;
            uint32_t bfr[8][2];
#pragma unroll
            for (int nj = 0; nj < 4; nj++) {
                uint32_t r0, r1, r2, r3;
                LDSM4(r0, r1, r2, r3, sb + A_BYTES + boff + nj * (16 * ROWB) + kk * 32);
                bfr[nj * 2][0] = r0;     bfr[nj * 2][1] = r1;
                bfr[nj * 2 + 1][0] = r2; bfr[nj * 2 + 1][1] = r3;
            }
            uint32_t ar[2][4];
#pragma unroll
            for (int ti = 0; ti < 2; ti++)
                LDSM4(ar[ti][0], ar[ti][1], ar[ti][2], ar[ti][3],
                      sb + aoff + ti * (16 * ROWB) + kk * 32);
#pragma unroll
            for (int mi = 0; mi < 2; mi++) {
                const uint32_t kp0 = *reinterpret_cast<const uint32_t*>(&kms[mi * DD + kb + c0]);
                const uint32_t kp1 = *reinterpret_cast<const uint32_t*>(&kms[mi * DD + kb + c0 + 8]);
#pragma unroll
                for (int ti = 0; ti < 2; ti++) {
                    uint32_t a0 = hmul2u(ar[ti][0], kp0);
                    uint32_t a1 = hmul2u(ar[ti][1], kp0);
                    uint32_t a2 = hmul2u(ar[ti][2], kp1);
                    uint32_t a3 = hmul2u(ar[ti][3], kp1);
#pragma unroll
                    for (int ni = 0; ni < 8; ni++)
                        MMA16816(acc[mi][ti][ni][0], acc[mi][ti][ni][1],
                                 a0, a1, a2, a3, bfr[ni][0], bfr[ni][1]);
                }
            }
        }
    };

    // Prologue: 3 stages in flight
    issue(0); asm volatile("cp.async.commit_group;" ::: "memory");
    issue(1); asm volatile("cp.async.commit_group;" ::: "memory");
    issue(2); asm volatile("cp.async.commit_group;" ::: "memory");

    for (int ki = 0; ki < NST; ki++) {
        asm volatile("cp.async.wait_group 2;" ::: "memory");
        __syncthreads();
        compute(ki);
        if (ki + 3 < NST) issue(ki + 3);
        asm volatile("cp.async.commit_group;" ::: "memory");
    }

    // Epilogue: max over this s-half, store pre-tanh to g_red[sh]
    float* red = reinterpret_cast<float*>(smem + S_RED);
    __syncthreads();
#pragma unroll
    for (int mi = 0; mi < 2; mi++)
#pragma unroll
        for (int ti = 0; ti < 2; ti++)
#pragma unroll
            for (int h = 0; h < 2; h++) {
                __half2 v = *reinterpret_cast<__half2*>(&acc[mi][ti][0][h]);
#pragma unroll
                for (int ni = 1; ni < 8; ni++)
                    v = __hmax2(v, *reinterpret_cast<__half2*>(&acc[mi][ti][ni][h]));
                float fm = fmaxf(__low2float(v), __high2float(v));
                fm = fmaxf(fm, __shfl_xor_sync(0xffffffffu, fm, 1));
                fm = fmaxf(fm, __shfl_xor_sync(0xffffffffu, fm, 2));
                if ((lane & 3) == 0) {
                    int row = wt * 32 + ti * 16 + h * 8 + (lane >> 2);
                    red[(mi * 128 + row) * 2 + ws] = fm;
                }
            }
    __syncthreads();
    {
        const int mi = tid >> 7, row = tid & 127;
        float v = fmaxf(red[(mi * 128 + row) * 2], red[(mi * 128 + row) * 2 + 1]);
        g_red[sh][(size_t)(b * TT + t0 + row) * MPP + (m0 + mi)] = v;
    }
}

// ---------------------------------------------------------------------------
// Kernel 3: combine halves, tanh, store
// ---------------------------------------------------------------------------
__global__ void fin_kernel(float* __restrict__ out) {
    int i = blockIdx.x * blockDim.x + threadIdx.x;
    out[i] = tanhf(fmaxf(g_red[0][i], g_red[1][i]));
}

// ---------------------------------------------------------------------------
// Launch: inputs: reps_lt[B,T,D] f32, reps_rt[B,T,D] f32, kernel[1,1,1,MP,D] f32.
// Output [B,T,MP] f32.
// ---------------------------------------------------------------------------
extern "C" void kernel_launch(void* const* d_in, const int* in_sizes, int n_in,
                              void* d_out, int out_size) {
    const float* lt = (const float*)d_in[0];
    const float* rt = (const float*)d_in[1];
    const float* kw = (const float*)d_in[2];
    float* out = (float*)d_out;

    const int n4 = (BB * TT * DD) / 4;  // 1,048,576 float4 units
    cvt_kernel<<<n4 / 256, 256>>>(lt, rt);

    cudaFuncSetAttribute(match_kernel,
                         cudaFuncAttributeMaxDynamicSharedMemorySize, S_TOTAL);
    dim3 grid(4, MPP / 2, BB);  // (2 t-tiles x 2 s-halves, 10, 32) = 1280 CTAs
    match_kernel<<<grid, 256, S_TOTAL>>>(kw);

    const int n = BB * TT * MPP;  // 163,840
    fin_kernel<<<n / 256, 256>>>(out);
}

// round 6
// speedup vs baseline: 3.9640x; 2.6000x over previous
#include <cuda_runtime.h>
#include <cuda_fp16.h>
#include <cstdint>

// Problem constants
#define BB  32
#define TT  256
#define DD  512
#define MPP 20

constexpr int TM     = 128;            // CTA t rows
constexpr int TN     = 64;             // s cols per chunk
constexpr int NCHK   = TT / TN;        // 4 s-chunks
constexpr int KC     = 32;             // k per pipeline stage
constexpr int NST    = DD / KC;        // 16 stages
constexpr int STAGES = 4;              // cp.async ring depth
constexpr int ROWB   = 80;             // padded smem row bytes (64B data + 16B pad)
constexpr int A_BYTES   = TM * ROWB;              // 10240
constexpr int B_BYTES   = TN * ROWB;              // 5120
constexpr int STG_BYTES = A_BYTES + B_BYTES;      // 15360

constexpr int S_KMS = 0;               // 2*512 halves = 2048 B
constexpr int S_BUF = 2048;            // 128B aligned
constexpr int S_TOTAL = S_BUF + STAGES * STG_BYTES;  // 63488 B

constexpr float THRESH = 10.0f;        // tanh(10) = 1 - 4.1e-9; monotone-safe exit

// static device scratch (allocation-free per harness rules)
__device__ __half g_lt[BB * TT * DD];
__device__ __half g_rt[BB * TT * DD];

static __device__ __forceinline__ uint32_t s2u(const void* p) {
    return (uint32_t)__cvta_generic_to_shared(p);
}

#define CP16(dst, src) \
    asm volatile("cp.async.cg.shared.global [%0], [%1], 16;" :: "r"(dst), "l"(src))

#define LDSM4(r0, r1, r2, r3, addr)                                              \
    asm volatile("ldmatrix.sync.aligned.m8n8.x4.shared.b16 {%0,%1,%2,%3}, [%4];" \
                 : "=r"(r0), "=r"(r1), "=r"(r2), "=r"(r3) : "r"(addr))

#define MMA16816(d0, d1, a0, a1, a2, a3, b0, b1)                                  \
    asm volatile("mma.sync.aligned.m16n8k16.row.col.f16.f16.f16.f16 "             \
                 "{%0,%1},{%2,%3,%4,%5},{%6,%7},{%0,%1};"                         \
                 : "+r"(d0), "+r"(d1)                                             \
                 : "r"(a0), "r"(a1), "r"(a2), "r"(a3), "r"(b0), "r"(b1))

static __device__ __forceinline__ uint32_t hmul2u(uint32_t a, uint32_t b) {
    __half2 r = __hmul2(*reinterpret_cast<__half2*>(&a),
                        *reinterpret_cast<__half2*>(&b));
    return *reinterpret_cast<uint32_t*>(&r);
}

// ---------------------------------------------------------------------------
// Kernel 1: fp32 -> fp16 conversion of lt and rt
// ---------------------------------------------------------------------------
__global__ void cvt_kernel(const float* __restrict__ lt, const float* __restrict__ rt) {
    int i = blockIdx.x * blockDim.x + threadIdx.x;  // over n/4 float4 units
    float4 a = reinterpret_cast<const float4*>(lt)[i];
    float4 b = reinterpret_cast<const float4*>(rt)[i];
    __half2* dl = reinterpret_cast<__half2*>(g_lt);
    __half2* dr = reinterpret_cast<__half2*>(g_rt);
    dl[2*i]   = __floats2half2_rn(a.x, a.y);
    dl[2*i+1] = __floats2half2_rn(a.z, a.w);
    dr[2*i]   = __floats2half2_rn(b.x, b.y);
    dr[2*i+1] = __floats2half2_rn(b.z, b.w);
}

// ---------------------------------------------------------------------------
// Kernel 2: one CTA = (b, t-tile 128, m-pair). s processed in chunks of 64
// with monotone-safe early exit: if every row's running max > THRESH, the
// remaining s-chunks cannot change tanh(max) by more than 4.1e-9 -> stop.
// Fallback computes all chunks exactly. 8 warps, warp tile 16t x 64s x 2m,
// fp16 HMMA fp16-acc, B frags shared across both m, km folded in registers.
// ---------------------------------------------------------------------------
__global__ __launch_bounds__(256, 2)
void match_kernel(const float* __restrict__ kw, float* __restrict__ out) {
    extern __shared__ __align__(128) char smem[];
    const int tid = threadIdx.x;
    const int b   = blockIdx.z;
    const int m0  = blockIdx.y * 2;
    const int t0  = blockIdx.x * TM;
    const uint32_t sbase = s2u(smem);
    const uint32_t sbuf  = sbase + S_BUF;

    // stage km rows (m0, m0+1) as fp16 (visible by first pre-compute barrier)
    __half* kms = reinterpret_cast<__half*>(smem + S_KMS);
#pragma unroll
    for (int e = tid; e < 2 * DD; e += 256) {
        int mi = e >> 9, c = e & (DD - 1);
        kms[e] = __float2half_rn(kw[(m0 + mi) * DD + c]);
    }

    const __half* ltb = g_lt + (size_t)(b * TT + t0) * DD;
    const __half* rtb = g_rt + (size_t)b * TT * DD;

    const int wid  = tid >> 5;    // warp = 16 t-rows
    const int lane = tid & 31;
    const int wt   = wid;         // 0..7

    const uint32_t aoff = (uint32_t)(wt * 16 + (lane & 15)) * ROWB + (lane >> 4) * 16;
    const uint32_t boff = (uint32_t)((lane & 7) + ((lane >> 4) << 3)) * ROWB
                        + ((lane >> 3) & 1) * 16;
    const int c0 = (lane & 3) * 2;   // k column base of this thread's A frag elems

    float runmax[2][2] = {{-3.4e38f, -3.4e38f}, {-3.4e38f, -3.4e38f}};

    auto issue = [&](int st, int chunk) {
        const uint32_t sb = sbuf + (st % STAGES) * STG_BYTES;
        const int k0 = st * KC;
#pragma unroll
        for (int i = 0; i < 2; i++) {   // A: 128 rows x 4 x 16B
            int c = tid + i * 256, row = c >> 2, sub = c & 3;
            CP16(sb + row * ROWB + sub * 16, ltb + row * DD + k0 + sub * 8);
        }
        {   // B: 64 rows x 4 x 16B
            int row = tid >> 2, sub = tid & 3;
            CP16(sb + A_BYTES + row * ROWB + sub * 16,
                 rtb + (chunk * TN + row) * DD + k0 + sub * 8);
        }
    };

    for (int chunk = 0; chunk < NCHK; chunk++) {
        uint32_t acc[2][8][2];           // [m][n-frag][reg] fp16x2
#pragma unroll
        for (int mi = 0; mi < 2; mi++)
#pragma unroll
            for (int ni = 0; ni < 8; ni++) {
                acc[mi][ni][0] = 0u; acc[mi][ni][1] = 0u;
            }

        // Prologue: 3 stages in flight
        issue(0, chunk); asm volatile("cp.async.commit_group;" ::: "memory");
        issue(1, chunk); asm volatile("cp.async.commit_group;" ::: "memory");
        issue(2, chunk); asm volatile("cp.async.commit_group;" ::: "memory");

        for (int ki = 0; ki < NST; ki++) {
            asm volatile("cp.async.wait_group 2;" ::: "memory");
            __syncthreads();
            const uint32_t sb = sbuf + (ki % STAGES) * STG_BYTES;
#pragma unroll
            for (int kk = 0; kk < 2; kk++) {
                const int kb = ki * KC + kk * 16;
                uint32_t bfr[8][2];
#pragma unroll
                for (int nj = 0; nj < 4; nj++) {
                    uint32_t r0, r1, r2, r3;
                    LDSM4(r0, r1, r2, r3,
                          sb + A_BYTES + boff + nj * (16 * ROWB) + kk * 32);
                    bfr[nj * 2][0] = r0;     bfr[nj * 2][1] = r1;
                    bfr[nj * 2 + 1][0] = r2; bfr[nj * 2 + 1][1] = r3;
                }
                uint32_t ar[4];
                LDSM4(ar[0], ar[1], ar[2], ar[3], sb + aoff + kk * 32);
#pragma unroll
                for (int mi = 0; mi < 2; mi++) {
                    const uint32_t kp0 =
                        *reinterpret_cast<const uint32_t*>(&kms[mi * DD + kb + c0]);
                    const uint32_t kp1 =
                        *reinterpret_cast<const uint32_t*>(&kms[mi * DD + kb + c0 + 8]);
                    uint32_t a0 = hmul2u(ar[0], kp0);
                    uint32_t a1 = hmul2u(ar[1], kp0);
                    uint32_t a2 = hmul2u(ar[2], kp1);
                    uint32_t a3 = hmul2u(ar[3], kp1);
#pragma unroll
                    for (int ni = 0; ni < 8; ni++)
                        MMA16816(acc[mi][ni][0], acc[mi][ni][1],
                                 a0, a1, a2, a3, bfr[ni][0], bfr[ni][1]);
                }
            }
            if (ki + 3 < NST) issue(ki + 3, chunk);
            asm volatile("cp.async.commit_group;" ::: "memory");
        }

        // chunk max -> running max; vote on early exit (monotone-safe)
        bool pred = true;
#pragma unroll
        for (int mi = 0; mi < 2; mi++)
#pragma unroll
            for (int h = 0; h < 2; h++) {   // h=0: row g; h=1: row g+8
                __half2 v = *reinterpret_cast<__half2*>(&acc[mi][0][h]);
#pragma unroll
                for (int ni = 1; ni < 8; ni++)
                    v = __hmax2(v, *reinterpret_cast<__half2*>(&acc[mi][ni][h]));
                float fm = fmaxf(__low2float(v), __high2float(v));
                fm = fmaxf(fm, __shfl_xor_sync(0xffffffffu, fm, 1));
                fm = fmaxf(fm, __shfl_xor_sync(0xffffffffu, fm, 2));
                runmax[mi][h] = fmaxf(runmax[mi][h], fm);
                pred = pred && (runmax[mi][h] > THRESH);
            }
        int done = __syncthreads_and((int)pred);   // also fences ring reuse
        if (done) break;
    }

    // write: each 4-lane group holds maxes for rows wt*16 + h*8 + (lane>>2)
    if ((lane & 3) == 0) {
        const int g = lane >> 2;
#pragma unroll
        for (int mi = 0; mi < 2; mi++)
#pragma unroll
            for (int h = 0; h < 2; h++) {
                int row = wt * 16 + h * 8 + g;
                out[(size_t)(b * TT + t0 + row) * MPP + (m0 + mi)] =
                    tanhf(runmax[mi][h]);
            }
    }
}

// ---------------------------------------------------------------------------
// Launch: inputs: reps_lt[B,T,D] f32, reps_rt[B,T,D] f32, kernel[1,1,1,MP,D] f32.
// Output [B,T,MP] f32.
// ---------------------------------------------------------------------------
extern "C" void kernel_launch(void* const* d_in, const int* in_sizes, int n_in,
                              void* d_out, int out_size) {
    const float* lt = (const float*)d_in[0];
    const float* rt = (const float*)d_in[1];
    const float* kw = (const float*)d_in[2];
    float* out = (float*)d_out;

    const int n4 = (BB * TT * DD) / 4;  // 1,048,576 float4 units
    cvt_kernel<<<n4 / 256, 256>>>(lt, rt);

    cudaFuncSetAttribute(match_kernel,
                         cudaFuncAttributeMaxDynamicSharedMemorySize, S_TOTAL);
    dim3 grid(TT / TM, MPP / 2, BB);  // (2, 10, 32) = 640 CTAs
    match_kernel<<<grid, 256, S_TOTAL>>>(kw, out);
}

// round 7
// speedup vs baseline: 5.4842x; 1.3835x over previous
#include <cuda_runtime.h>
#include <cuda_fp16.h>
#include <cstdint>

// Problem constants
#define BB  32
#define TT  256
#define DD  512
#define MPP 20

constexpr int TM     = 128;            // CTA t rows
constexpr int TN     = 32;             // s cols per verified chunk
constexpr int NCHK   = TT / TN;        // 8 s-chunks
constexpr int KC     = 64;             // k per pipeline stage (4 x k16)
constexpr int NST    = DD / KC;        // 8 stages
constexpr int STAGES = 4;              // cp.async ring depth
constexpr int ROWB   = 144;            // smem row bytes: 128B data + 16B pad
constexpr int A_BYTES   = TM * ROWB;              // 18432
constexpr int B_BYTES   = TN * ROWB;              // 4608
constexpr int STG_BYTES = A_BYTES + B_BYTES;      // 23040

constexpr int S_KMS = 0;               // 2*512 halves = 2048 B
constexpr int S_BUF = 2048;            // 128B aligned
constexpr int S_TOTAL = S_BUF + STAGES * STG_BYTES;  // 94208 B

constexpr float THRESH = 10.0f;        // tanh(10) = 1 - 4.1e-9; monotone-safe exit

// static device scratch (allocation-free per harness rules)
__device__ __half g_lt[BB * TT * DD];
__device__ __half g_rt[BB * TT * DD];

static __device__ __forceinline__ uint32_t s2u(const void* p) {
    return (uint32_t)__cvta_generic_to_shared(p);
}

#define CP16(dst, src) \
    asm volatile("cp.async.cg.shared.global [%0], [%1], 16;" :: "r"(dst), "l"(src))

#define LDSM4(r0, r1, r2, r3, addr)                                              \
    asm volatile("ldmatrix.sync.aligned.m8n8.x4.shared.b16 {%0,%1,%2,%3}, [%4];" \
                 : "=r"(r0), "=r"(r1), "=r"(r2), "=r"(r3) : "r"(addr))

#define MMA16816(d0, d1, a0, a1, a2, a3, b0, b1)                                  \
    asm volatile("mma.sync.aligned.m16n8k16.row.col.f16.f16.f16.f16 "             \
                 "{%0,%1},{%2,%3,%4,%5},{%6,%7},{%0,%1};"                         \
                 : "+r"(d0), "+r"(d1)                                             \
                 : "r"(a0), "r"(a1), "r"(a2), "r"(a3), "r"(b0), "r"(b1))

static __device__ __forceinline__ uint32_t hmul2u(uint32_t a, uint32_t b) {
    __half2 r = __hmul2(*reinterpret_cast<__half2*>(&a),
                        *reinterpret_cast<__half2*>(&b));
    return *reinterpret_cast<uint32_t*>(&r);
}

// ---------------------------------------------------------------------------
// Kernel 1: fp32 -> fp16 conversion of lt and rt
// ---------------------------------------------------------------------------
__global__ void cvt_kernel(const float* __restrict__ lt, const float* __restrict__ rt) {
    int i = blockIdx.x * blockDim.x + threadIdx.x;  // over n/4 float4 units
    float4 a = reinterpret_cast<const float4*>(lt)[i];
    float4 b = reinterpret_cast<const float4*>(rt)[i];
    __half2* dl = reinterpret_cast<__half2*>(g_lt);
    __half2* dr = reinterpret_cast<__half2*>(g_rt);
    dl[2*i]   = __floats2half2_rn(a.x, a.y);
    dl[2*i+1] = __floats2half2_rn(a.z, a.w);
    dr[2*i]   = __floats2half2_rn(b.x, b.y);
    dr[2*i+1] = __floats2half2_rn(b.z, b.w);
}

// ---------------------------------------------------------------------------
// Kernel 2: one CTA = (b, t-tile 128, m-pair). s in chunks of 32 with
// monotone-safe early exit (exact fallback over all 8 chunks). 8 warps,
// warp tile 16t x 32s x 2m, fp16 HMMA fp16-acc, km folded in registers,
// B frags shared across both m. KC=64 stages (8 barriers/chunk), register
// double-buffered fragments.
// ---------------------------------------------------------------------------
__global__ __launch_bounds__(256, 2)
void match_kernel(const float* __restrict__ kw, float* __restrict__ out) {
    extern __shared__ __align__(128) char smem[];
    const int tid = threadIdx.x;
    const int b   = blockIdx.z;
    const int m0  = blockIdx.y * 2;
    const int t0  = blockIdx.x * TM;
    const uint32_t sbase = s2u(smem);
    const uint32_t sbuf  = sbase + S_BUF;

    // stage km rows (m0, m0+1) as fp16 (visible by first pre-compute barrier)
    __half* kms = reinterpret_cast<__half*>(smem + S_KMS);
#pragma unroll
    for (int e = tid; e < 2 * DD; e += 256) {
        int mi = e >> 9, c = e & (DD - 1);
        kms[e] = __float2half_rn(kw[(m0 + mi) * DD + c]);
    }

    const __half* ltb = g_lt + (size_t)(b * TT + t0) * DD;
    const __half* rtb = g_rt + (size_t)b * TT * DD;

    const int wid  = tid >> 5;    // warp = 16 t-rows
    const int lane = tid & 31;
    const int wt   = wid;         // 0..7

    const uint32_t aoff = (uint32_t)(wt * 16 + (lane & 15)) * ROWB + (lane >> 4) * 16;
    const uint32_t boff = (uint32_t)((lane & 7) + ((lane >> 4) << 3)) * ROWB
                        + ((lane >> 3) & 1) * 16;
    const int c0 = (lane & 3) * 2;   // k column base of this thread's A frag elems

    float runmax[2][2] = {{-3.4e38f, -3.4e38f}, {-3.4e38f, -3.4e38f}};

    auto issue = [&](int st, int chunk) {
        const uint32_t sb = sbuf + (st % STAGES) * STG_BYTES;
        const int k0 = st * KC;
#pragma unroll
        for (int i = 0; i < 4; i++) {   // A: 128 rows x 8 x 16B = 1024 chunks
            int c = tid + i * 256, row = c >> 3, sub = c & 7;
            CP16(sb + row * ROWB + sub * 16, ltb + row * DD + k0 + sub * 8);
        }
        {   // B: 32 rows x 8 x 16B = 256 chunks
            int row = tid >> 3, sub = tid & 7;
            CP16(sb + A_BYTES + row * ROWB + sub * 16,
                 rtb + (chunk * TN + row) * DD + k0 + sub * 8);
        }
    };

    // fragment load for one k16 slice kk (0..3) of stage buffer sb
    auto ldfrag = [&](uint32_t sb, int kk, uint32_t* bf, uint32_t* af) {
        LDSM4(bf[0], bf[1], bf[2], bf[3], sb + A_BYTES + boff + kk * 32);
        LDSM4(bf[4], bf[5], bf[6], bf[7], sb + A_BYTES + boff + 16 * ROWB + kk * 32);
        LDSM4(af[0], af[1], af[2], af[3], sb + aoff + kk * 32);
    };

    for (int chunk = 0; chunk < NCHK; chunk++) {
        uint32_t acc[2][4][2];           // [m][n-frag][reg] fp16x2
#pragma unroll
        for (int mi = 0; mi < 2; mi++)
#pragma unroll
            for (int ni = 0; ni < 4; ni++) {
                acc[mi][ni][0] = 0u; acc[mi][ni][1] = 0u;
            }

        // Prologue: 3 stages in flight
        issue(0, chunk); asm volatile("cp.async.commit_group;" ::: "memory");
        issue(1, chunk); asm volatile("cp.async.commit_group;" ::: "memory");
        issue(2, chunk); asm volatile("cp.async.commit_group;" ::: "memory");

        for (int ki = 0; ki < NST; ki++) {
            asm volatile("cp.async.wait_group 2;" ::: "memory");
            __syncthreads();
            const uint32_t sb = sbuf + (ki % STAGES) * STG_BYTES;

            uint32_t bfA[8], afA[4], bfB[8], afB[4];
            ldfrag(sb, 0, bfA, afA);
#pragma unroll
            for (int kk = 0; kk < 4; kk++) {
                uint32_t* bf = (kk & 1) ? bfB : bfA;
                uint32_t* af = (kk & 1) ? afB : afA;
                if (kk < 3) ldfrag(sb, kk + 1, (kk & 1) ? bfA : bfB,
                                               (kk & 1) ? afA : afB);
                const int kb = ki * KC + kk * 16;
#pragma unroll
                for (int mi = 0; mi < 2; mi++) {
                    const uint32_t kp0 =
                        *reinterpret_cast<const uint32_t*>(&kms[mi * DD + kb + c0]);
                    const uint32_t kp1 =
                        *reinterpret_cast<const uint32_t*>(&kms[mi * DD + kb + c0 + 8]);
                    uint32_t a0 = hmul2u(af[0], kp0);
                    uint32_t a1 = hmul2u(af[1], kp0);
                    uint32_t a2 = hmul2u(af[2], kp1);
                    uint32_t a3 = hmul2u(af[3], kp1);
#pragma unroll
                    for (int ni = 0; ni < 4; ni++)
                        MMA16816(acc[mi][ni][0], acc[mi][ni][1],
                                 a0, a1, a2, a3, bf[ni * 2], bf[ni * 2 + 1]);
                }
            }
            if (ki + 3 < NST) issue(ki + 3, chunk);
            asm volatile("cp.async.commit_group;" ::: "memory");
        }

        // chunk max -> running max; vote on early exit (monotone-safe)
        bool pred = true;
#pragma unroll
        for (int mi = 0; mi < 2; mi++)
#pragma unroll
            for (int h = 0; h < 2; h++) {   // h=0: row g; h=1: row g+8
                __half2 v = *reinterpret_cast<__half2*>(&acc[mi][0][h]);
#pragma unroll
                for (int ni = 1; ni < 4; ni++)
                    v = __hmax2(v, *reinterpret_cast<__half2*>(&acc[mi][ni][h]));
                float fm = fmaxf(__low2float(v), __high2float(v));
                fm = fmaxf(fm, __shfl_xor_sync(0xffffffffu, fm, 1));
                fm = fmaxf(fm, __shfl_xor_sync(0xffffffffu, fm, 2));
                runmax[mi][h] = fmaxf(runmax[mi][h], fm);
                pred = pred && (runmax[mi][h] > THRESH);
            }
        int done = __syncthreads_and((int)pred);   // also fences ring reuse
        if (done) break;
    }

    // write: each 4-lane group holds maxes for rows wt*16 + h*8 + (lane>>2)
    if ((lane & 3) == 0) {
        const int g = lane >> 2;
#pragma unroll
        for (int mi = 0; mi < 2; mi++)
#pragma unroll
            for (int h = 0; h < 2; h++) {
                int row = wt * 16 + h * 8 + g;
                out[(size_t)(b * TT + t0 + row) * MPP + (m0 + mi)] =
                    tanhf(runmax[mi][h]);
            }
    }
}

// ---------------------------------------------------------------------------
// Launch: inputs: reps_lt[B,T,D] f32, reps_rt[B,T,D] f32, kernel[1,1,1,MP,D] f32.
// Output [B,T,MP] f32.
// ---------------------------------------------------------------------------
extern "C" void kernel_launch(void* const* d_in, const int* in_sizes, int n_in,
                              void* d_out, int out_size) {
    const float* lt = (const float*)d_in[0];
    const float* rt = (const float*)d_in[1];
    const float* kw = (const float*)d_in[2];
    float* out = (float*)d_out;

    const int n4 = (BB * TT * DD) / 4;  // 1,048,576 float4 units
    cvt_kernel<<<n4 / 256, 256>>>(lt, rt);

    cudaFuncSetAttribute(match_kernel,
                         cudaFuncAttributeMaxDynamicSharedMemorySize, S_TOTAL);
    dim3 grid(TT / TM, MPP / 2, BB);  // (2, 10, 32) = 640 CTAs
    match_kernel<<<grid, 256, S_TOTAL>>>(kw, out);
}

// round 8
// speedup vs baseline: 5.8662x; 1.0696x over previous
#include <cuda_runtime.h>
#include <cuda_fp16.h>
#include <cstdint>

// Problem constants
#define BB  32
#define TT  256
#define DD  512
#define MPP 20

constexpr int TM     = 128;            // CTA t rows
constexpr int TN     = 32;             // s cols per verified chunk
constexpr int NCHK   = TT / TN;        // 8 s-chunks
constexpr int NM     = 4;              // m-planes per CTA
constexpr int KC     = 64;             // k per pipeline stage (4 x k16)
constexpr int NST    = DD / KC;        // 8 stages
constexpr int STAGES = 4;              // cp.async ring depth
constexpr int ROWB   = 144;            // smem row bytes: 128B data + 16B pad
constexpr int A_BYTES   = TM * ROWB;              // 18432
constexpr int B_BYTES   = TN * ROWB;              // 4608
constexpr int STG_BYTES = A_BYTES + B_BYTES;      // 23040

constexpr int S_KMS = 0;               // 4*512 halves = 4096 B
constexpr int S_BUF = 4096;            // 128B aligned
constexpr int S_TOTAL = S_BUF + STAGES * STG_BYTES;  // 96256 B

constexpr float THRESH = 10.0f;        // tanh(10) = 1 - 4.1e-9; monotone-safe exit

// static device scratch (allocation-free per harness rules)
__device__ __half g_lt[BB * TT * DD];
__device__ __half g_rt[BB * TT * DD];

static __device__ __forceinline__ uint32_t s2u(const void* p) {
    return (uint32_t)__cvta_generic_to_shared(p);
}

#define CP16(dst, src) \
    asm volatile("cp.async.cg.shared.global [%0], [%1], 16;" :: "r"(dst), "l"(src))

#define LDSM4(r0, r1, r2, r3, addr)                                              \
    asm volatile("ldmatrix.sync.aligned.m8n8.x4.shared.b16 {%0,%1,%2,%3}, [%4];" \
                 : "=r"(r0), "=r"(r1), "=r"(r2), "=r"(r3) : "r"(addr))

#define MMA16816(d0, d1, a0, a1, a2, a3, b0, b1)                                  \
    asm volatile("mma.sync.aligned.m16n8k16.row.col.f16.f16.f16.f16 "             \
                 "{%0,%1},{%2,%3,%4,%5},{%6,%7},{%0,%1};"                         \
                 : "+r"(d0), "+r"(d1)                                             \
                 : "r"(a0), "r"(a1), "r"(a2), "r"(a3), "r"(b0), "r"(b1))

static __device__ __forceinline__ uint32_t hmul2u(uint32_t a, uint32_t b) {
    __half2 r = __hmul2(*reinterpret_cast<__half2*>(&a),
                        *reinterpret_cast<__half2*>(&b));
    return *reinterpret_cast<uint32_t*>(&r);
}

// ---------------------------------------------------------------------------
// Kernel 1: fp32 -> fp16 conversion of lt and rt
// ---------------------------------------------------------------------------
__global__ void cvt_kernel(const float* __restrict__ lt, const float* __restrict__ rt) {
    int i = blockIdx.x * blockDim.x + threadIdx.x;  // over n/4 float4 units
    float4 a = reinterpret_cast<const float4*>(lt)[i];
    float4 b = reinterpret_cast<const float4*>(rt)[i];
    __half2* dl = reinterpret_cast<__half2*>(g_lt);
    __half2* dr = reinterpret_cast<__half2*>(g_rt);
    dl[2*i]   = __floats2half2_rn(a.x, a.y);
    dl[2*i+1] = __floats2half2_rn(a.z, a.w);
    dr[2*i]   = __floats2half2_rn(b.x, b.y);
    dr[2*i+1] = __floats2half2_rn(b.z, b.w);
}

// ---------------------------------------------------------------------------
// Kernel 2: one CTA = (b, t-tile 128, m-quad). s in chunks of 32 with
// monotone-safe early exit (exact fallback over all 8 chunks). 8 warps,
// warp tile 16t x 32s x 4m, fp16 HMMA fp16-acc, km folded in registers,
// A/B frags shared across all 4 m. KC=64 stages, register double-buffered
// fragments, 4-stage cp.async ring.
// ---------------------------------------------------------------------------
__global__ __launch_bounds__(256, 2)
void match_kernel(const float* __restrict__ kw, float* __restrict__ out) {
    extern __shared__ __align__(128) char smem[];
    const int tid = threadIdx.x;
    const int b   = blockIdx.z;
    const int m0  = blockIdx.y * NM;
    const int t0  = blockIdx.x * TM;
    const uint32_t sbase = s2u(smem);
    const uint32_t sbuf  = sbase + S_BUF;

    // stage km rows (m0..m0+3) as fp16 (visible by first pre-compute barrier)
    __half* kms = reinterpret_cast<__half*>(smem + S_KMS);
#pragma unroll
    for (int e = tid; e < NM * DD; e += 256) {
        int mi = e >> 9, c = e & (DD - 1);
        kms[e] = __float2half_rn(kw[(m0 + mi) * DD + c]);
    }

    const __half* ltb = g_lt + (size_t)(b * TT + t0) * DD;
    const __half* rtb = g_rt + (size_t)b * TT * DD;

    const int wid  = tid >> 5;    // warp = 16 t-rows
    const int lane = tid & 31;
    const int wt   = wid;         // 0..7

    const uint32_t aoff = (uint32_t)(wt * 16 + (lane & 15)) * ROWB + (lane >> 4) * 16;
    const uint32_t boff = (uint32_t)((lane & 7) + ((lane >> 4) << 3)) * ROWB
                        + ((lane >> 3) & 1) * 16;
    const int c0 = (lane & 3) * 2;   // k column base of this thread's A frag elems

    float runmax[NM][2];
#pragma unroll
    for (int mi = 0; mi < NM; mi++) { runmax[mi][0] = -3.4e38f; runmax[mi][1] = -3.4e38f; }

    auto issue = [&](int st, int chunk) {
        const uint32_t sb = sbuf + (st % STAGES) * STG_BYTES;
        const int k0 = st * KC;
#pragma unroll
        for (int i = 0; i < 4; i++) {   // A: 128 rows x 8 x 16B = 1024 chunks
            int c = tid + i * 256, row = c >> 3, sub = c & 7;
            CP16(sb + row * ROWB + sub * 16, ltb + row * DD + k0 + sub * 8);
        }
        {   // B: 32 rows x 8 x 16B = 256 chunks
            int row = tid >> 3, sub = tid & 7;
            CP16(sb + A_BYTES + row * ROWB + sub * 16,
                 rtb + (chunk * TN + row) * DD + k0 + sub * 8);
        }
    };

    // fragment load for one k16 slice kk (0..3) of stage buffer sb
    auto ldfrag = [&](uint32_t sb, int kk, uint32_t* bf, uint32_t* af) {
        LDSM4(bf[0], bf[1], bf[2], bf[3], sb + A_BYTES + boff + kk * 32);
        LDSM4(bf[4], bf[5], bf[6], bf[7], sb + A_BYTES + boff + 16 * ROWB + kk * 32);
        LDSM4(af[0], af[1], af[2], af[3], sb + aoff + kk * 32);
    };

    for (int chunk = 0; chunk < NCHK; chunk++) {
        uint32_t acc[NM][4][2];          // [m][n-frag][reg] fp16x2
#pragma unroll
        for (int mi = 0; mi < NM; mi++)
#pragma unroll
            for (int ni = 0; ni < 4; ni++) {
                acc[mi][ni][0] = 0u; acc[mi][ni][1] = 0u;
            }

        // Prologue: 3 stages in flight
        issue(0, chunk); asm volatile("cp.async.commit_group;" ::: "memory");
        issue(1, chunk); asm volatile("cp.async.commit_group;" ::: "memory");
        issue(2, chunk); asm volatile("cp.async.commit_group;" ::: "memory");

        for (int ki = 0; ki < NST; ki++) {
            asm volatile("cp.async.wait_group 2;" ::: "memory");
            __syncthreads();
            const uint32_t sb = sbuf + (ki % STAGES) * STG_BYTES;

            uint32_t bfA[8], afA[4], bfB[8], afB[4];
            ldfrag(sb, 0, bfA, afA);
#pragma unroll
            for (int kk = 0; kk < 4; kk++) {
                uint32_t* bf = (kk & 1) ? bfB : bfA;
                uint32_t* af = (kk & 1) ? afB : afA;
                if (kk < 3) ldfrag(sb, kk + 1, (kk & 1) ? bfA : bfB,
                                               (kk & 1) ? afA : afB);
                const int kb = ki * KC + kk * 16;
#pragma unroll
                for (int mi = 0; mi < NM; mi++) {
                    const uint32_t kp0 =
                        *reinterpret_cast<const uint32_t*>(&kms[mi * DD + kb + c0]);
                    const uint32_t kp1 =
                        *reinterpret_cast<const uint32_t*>(&kms[mi * DD + kb + c0 + 8]);
                    uint32_t a0 = hmul2u(af[0], kp0);
                    uint32_t a1 = hmul2u(af[1], kp0);
                    uint32_t a2 = hmul2u(af[2], kp1);
                    uint32_t a3 = hmul2u(af[3], kp1);
#pragma unroll
                    for (int ni = 0; ni < 4; ni++)
                        MMA16816(acc[mi][ni][0], acc[mi][ni][1],
                                 a0, a1, a2, a3, bf[ni * 2], bf[ni * 2 + 1]);
                }
            }
            if (ki + 3 < NST) issue(ki + 3, chunk);
            asm volatile("cp.async.commit_group;" ::: "memory");
        }

        // chunk max -> running max; vote on early exit (monotone-safe)
        bool pred = true;
#pragma unroll
        for (int mi = 0; mi < NM; mi++)
#pragma unroll
            for (int h = 0; h < 2; h++) {   // h=0: row g; h=1: row g+8
                __half2 v = *reinterpret_cast<__half2*>(&acc[mi][0][h]);
#pragma unroll
                for (int ni = 1; ni < 4; ni++)
                    v = __hmax2(v, *reinterpret_cast<__half2*>(&acc[mi][ni][h]));
                float fm = fmaxf(__low2float(v), __high2float(v));
                fm = fmaxf(fm, __shfl_xor_sync(0xffffffffu, fm, 1));
                fm = fmaxf(fm, __shfl_xor_sync(0xffffffffu, fm, 2));
                runmax[mi][h] = fmaxf(runmax[mi][h], fm);
                pred = pred && (runmax[mi][h] > THRESH);
            }
        int done = __syncthreads_and((int)pred);   // also fences ring reuse
        if (done) break;
    }

    // write: each 4-lane group holds maxes for rows wt*16 + h*8 + (lane>>2)
    if ((lane & 3) == 0) {
        const int g = lane >> 2;
#pragma unroll
        for (int mi = 0; mi < NM; mi++)
#pragma unroll
            for (int h = 0; h < 2; h++) {
                int row = wt * 16 + h * 8 + g;
                out[(size_t)(b * TT + t0 + row) * MPP + (m0 + mi)] =
                    tanhf(runmax[mi][h]);
            }
    }
}

// ---------------------------------------------------------------------------
// Launch: inputs: reps_lt[B,T,D] f32, reps_rt[B,T,D] f32, kernel[1,1,1,MP,D] f32.
// Output [B,T,MP] f32.
// ---------------------------------------------------------------------------
extern "C" void kernel_launch(void* const* d_in, const int* in_sizes, int n_in,
                              void* d_out, int out_size) {
    const float* lt = (const float*)d_in[0];
    const float* rt = (const float*)d_in[1];
    const float* kw = (const float*)d_in[2];
    float* out = (float*)d_out;

    const int n4 = (BB * TT * DD) / 4;  // 1,048,576 float4 units
    cvt_kernel<<<n4 / 256, 256>>>(lt, rt);

    cudaFuncSetAttribute(match_kernel,
                         cudaFuncAttributeMaxDynamicSharedMemorySize, S_TOTAL);
    dim3 grid(TT / TM, MPP / NM, BB);  // (2, 5, 32) = 320 CTAs
    match_kernel<<<grid, 256, S_TOTAL>>>(kw, out);
}

// round 9
// speedup vs baseline: 6.3126x; 1.0761x over previous
#include <cuda_runtime.h>
#include <cuda_fp16.h>
#include <cstdint>

// Problem constants
#define BB  32
#define TT  256
#define DD  512
#define MPP 20

constexpr int TM     = 128;            // CTA t rows
constexpr int TN     = 32;             // s cols per verified chunk
constexpr int NCHK   = TT / TN;        // 8 s-chunks
constexpr int NM     = 5;              // m-planes per CTA (20 = 4 groups of 5)
constexpr int KC     = 64;             // k per pipeline stage (4 x k16)
constexpr int NST    = DD / KC;        // 8 stages
constexpr int STAGES = 4;              // cp.async ring depth
constexpr int ROWB   = 144;            // smem row bytes: 128B data + 16B pad
constexpr int A_BYTES   = TM * ROWB;              // 18432
constexpr int B_BYTES   = TN * ROWB;              // 4608
constexpr int STG_BYTES = A_BYTES + B_BYTES;      // 23040

constexpr int S_KMS = 0;               // 5*512 halves = 5120 B
constexpr int S_BUF = 5120;            // 128B aligned
constexpr int S_TOTAL = S_BUF + STAGES * STG_BYTES;  // 97280 B

constexpr float THRESH = 10.0f;        // tanh(10) = 1 - 4.1e-9; monotone-safe exit

// static device scratch (allocation-free per harness rules)
__device__ __half g_lt[BB * TT * DD];
__device__ __half g_rt[BB * TT * DD];

static __device__ __forceinline__ uint32_t s2u(const void* p) {
    return (uint32_t)__cvta_generic_to_shared(p);
}

#define CP16(dst, src) \
    asm volatile("cp.async.cg.shared.global [%0], [%1], 16;" :: "r"(dst), "l"(src))

#define LDSM4(r0, r1, r2, r3, addr)                                              \
    asm volatile("ldmatrix.sync.aligned.m8n8.x4.shared.b16 {%0,%1,%2,%3}, [%4];" \
                 : "=r"(r0), "=r"(r1), "=r"(r2), "=r"(r3) : "r"(addr))

#define MMA16816(d0, d1, a0, a1, a2, a3, b0, b1)                                  \
    asm volatile("mma.sync.aligned.m16n8k16.row.col.f16.f16.f16.f16 "             \
                 "{%0,%1},{%2,%3,%4,%5},{%6,%7},{%0,%1};"                         \
                 : "+r"(d0), "+r"(d1)                                             \
                 : "r"(a0), "r"(a1), "r"(a2), "r"(a3), "r"(b0), "r"(b1))

static __device__ __forceinline__ uint32_t hmul2u(uint32_t a, uint32_t b) {
    __half2 r = __hmul2(*reinterpret_cast<__half2*>(&a),
                        *reinterpret_cast<__half2*>(&b));
    return *reinterpret_cast<uint32_t*>(&r);
}

// ---------------------------------------------------------------------------
// Kernel 1: fp32 -> fp16 conversion of lt and rt
// ---------------------------------------------------------------------------
__global__ void cvt_kernel(const float* __restrict__ lt, const float* __restrict__ rt) {
    int i = blockIdx.x * blockDim.x + threadIdx.x;  // over n/4 float4 units
    float4 a = reinterpret_cast<const float4*>(lt)[i];
    float4 b = reinterpret_cast<const float4*>(rt)[i];
    __half2* dl = reinterpret_cast<__half2*>(g_lt);
    __half2* dr = reinterpret_cast<__half2*>(g_rt);
    dl[2*i]   = __floats2half2_rn(a.x, a.y);
    dl[2*i+1] = __floats2half2_rn(a.z, a.w);
    dr[2*i]   = __floats2half2_rn(b.x, b.y);
    dr[2*i+1] = __floats2half2_rn(b.z, b.w);
}

// ---------------------------------------------------------------------------
// Kernel 2: one CTA = (b, t-tile 128, 5 m-planes). s in chunks of 32 with
// monotone-safe early exit (exact fallback over all 8 chunks). 8 warps,
// warp tile 16t x 32s x 5m, fp16 HMMA fp16-acc, km folded in registers,
// A/B frags shared across all 5 m. Grid = 256 CTAs <= 296 slots: no SM
// runs a third sequential CTA (slot-quantized makespan fix).
// ---------------------------------------------------------------------------
__global__ __launch_bounds__(256, 2)
void match_kernel(const float* __restrict__ kw, float* __restrict__ out) {
    extern __shared__ __align__(128) char smem[];
    const int tid = threadIdx.x;
    const int b   = blockIdx.z;
    const int m0  = blockIdx.y * NM;
    const int t0  = blockIdx.x * TM;
    const uint32_t sbase = s2u(smem);
    const uint32_t sbuf  = sbase + S_BUF;

    // stage km rows (m0..m0+4) as fp16 (visible by first pre-compute barrier)
    __half* kms = reinterpret_cast<__half*>(smem + S_KMS);
#pragma unroll
    for (int e = tid; e < NM * DD; e += 256) {
        int mi = e >> 9, c = e & (DD - 1);
        kms[e] = __float2half_rn(kw[(m0 + mi) * DD + c]);
    }

    const __half* ltb = g_lt + (size_t)(b * TT + t0) * DD;
    const __half* rtb = g_rt + (size_t)b * TT * DD;

    const int wid  = tid >> 5;    // warp = 16 t-rows
    const int lane = tid & 31;
    const int wt   = wid;         // 0..7

    const uint32_t aoff = (uint32_t)(wt * 16 + (lane & 15)) * ROWB + (lane >> 4) * 16;
    const uint32_t boff = (uint32_t)((lane & 7) + ((lane >> 4) << 3)) * ROWB
                        + ((lane >> 3) & 1) * 16;
    const int c0 = (lane & 3) * 2;   // k column base of this thread's A frag elems

    float runmax[NM][2];
#pragma unroll
    for (int mi = 0; mi < NM; mi++) { runmax[mi][0] = -3.4e38f; runmax[mi][1] = -3.4e38f; }

    auto issue = [&](int st, int chunk) {
        const uint32_t sb = sbuf + (st % STAGES) * STG_BYTES;
        const int k0 = st * KC;
#pragma unroll
        for (int i = 0; i < 4; i++) {   // A: 128 rows x 8 x 16B = 1024 chunks
            int c = tid + i * 256, row = c >> 3, sub = c & 7;
            CP16(sb + row * ROWB + sub * 16, ltb + row * DD + k0 + sub * 8);
        }
        {   // B: 32 rows x 8 x 16B = 256 chunks
            int row = tid >> 3, sub = tid & 7;
            CP16(sb + A_BYTES + row * ROWB + sub * 16,
                 rtb + (chunk * TN + row) * DD + k0 + sub * 8);
        }
    };

    // fragment load for one k16 slice kk (0..3) of stage buffer sb
    auto ldfrag = [&](uint32_t sb, int kk, uint32_t* bf, uint32_t* af) {
        LDSM4(bf[0], bf[1], bf[2], bf[3], sb + A_BYTES + boff + kk * 32);
        LDSM4(bf[4], bf[5], bf[6], bf[7], sb + A_BYTES + boff + 16 * ROWB + kk * 32);
        LDSM4(af[0], af[1], af[2], af[3], sb + aoff + kk * 32);
    };

    for (int chunk = 0; chunk < NCHK; chunk++) {
        uint32_t acc[NM][4][2];          // [m][n-frag][reg] fp16x2
#pragma unroll
        for (int mi = 0; mi < NM; mi++)
#pragma unroll
            for (int ni = 0; ni < 4; ni++) {
                acc[mi][ni][0] = 0u; acc[mi][ni][1] = 0u;
            }

        // Prologue: 3 stages in flight
        issue(0, chunk); asm volatile("cp.async.commit_group;" ::: "memory");
        issue(1, chunk); asm volatile("cp.async.commit_group;" ::: "memory");
        issue(2, chunk); asm volatile("cp.async.commit_group;" ::: "memory");

        for (int ki = 0; ki < NST; ki++) {
            asm volatile("cp.async.wait_group 2;" ::: "memory");
            __syncthreads();
            const uint32_t sb = sbuf + (ki % STAGES) * STG_BYTES;

            uint32_t bfA[8], afA[4], bfB[8], afB[4];
            ldfrag(sb, 0, bfA, afA);
#pragma unroll
            for (int kk = 0; kk < 4; kk++) {
                uint32_t* bf = (kk & 1) ? bfB : bfA;
                uint32_t* af = (kk & 1) ? afB : afA;
                if (kk < 3) ldfrag(sb, kk + 1, (kk & 1) ? bfA : bfB,
                                               (kk & 1) ? afA : afB);
                const int kb = ki * KC + kk * 16;
#pragma unroll
                for (int mi = 0; mi < NM; mi++) {
                    const uint32_t kp0 =
                        *reinterpret_cast<const uint32_t*>(&kms[mi * DD + kb + c0]);
                    const uint32_t kp1 =
                        *reinterpret_cast<const uint32_t*>(&kms[mi * DD + kb + c0 + 8]);
                    uint32_t a0 = hmul2u(af[0], kp0);
                    uint32_t a1 = hmul2u(af[1], kp0);
                    uint32_t a2 = hmul2u(af[2], kp1);
                    uint32_t a3 = hmul2u(af[3], kp1);
#pragma unroll
                    for (int ni = 0; ni < 4; ni++)
                        MMA16816(acc[mi][ni][0], acc[mi][ni][1],
                                 a0, a1, a2, a3, bf[ni * 2], bf[ni * 2 + 1]);
                }
            }
            if (ki + 3 < NST) issue(ki + 3, chunk);
            asm volatile("cp.async.commit_group;" ::: "memory");
        }

        // chunk max -> running max; vote on early exit (monotone-safe)
        bool pred = true;
#pragma unroll
        for (int mi = 0; mi < NM; mi++)
#pragma unroll
            for (int h = 0; h < 2; h++) {   // h=0: row g; h=1: row g+8
                __half2 v = *reinterpret_cast<__half2*>(&acc[mi][0][h]);
#pragma unroll
                for (int ni = 1; ni < 4; ni++)
                    v = __hmax2(v, *reinterpret_cast<__half2*>(&acc[mi][ni][h]));
                float fm = fmaxf(__low2float(v), __high2float(v));
                fm = fmaxf(fm, __shfl_xor_sync(0xffffffffu, fm, 1));
                fm = fmaxf(fm, __shfl_xor_sync(0xffffffffu, fm, 2));
                runmax[mi][h] = fmaxf(runmax[mi][h], fm);
                pred = pred && (runmax[mi][h] > THRESH);
            }
        int done = __syncthreads_and((int)pred);   // also fences ring reuse
        if (done) break;
    }

    // write: each 4-lane group holds maxes for rows wt*16 + h*8 + (lane>>2)
    if ((lane & 3) == 0) {
        const int g = lane >> 2;
#pragma unroll
        for (int mi = 0; mi < NM; mi++)
#pragma unroll
            for (int h = 0; h < 2; h++) {
                int row = wt * 16 + h * 8 + g;
                out[(size_t)(b * TT + t0 + row) * MPP + (m0 + mi)] =
                    tanhf(runmax[mi][h]);
            }
    }
}

// ---------------------------------------------------------------------------
// Launch: inputs: reps_lt[B,T,D] f32, reps_rt[B,T,D] f32, kernel[1,1,1,MP,D] f32.
// Output [B,T,MP] f32.
// ---------------------------------------------------------------------------
extern "C" void kernel_launch(void* const* d_in, const int* in_sizes, int n_in,
                              void* d_out, int out_size) {
    const float* lt = (const float*)d_in[0];
    const float* rt = (const float*)d_in[1];
    const float* kw = (const float*)d_in[2];
    float* out = (float*)d_out;

    const int n4 = (BB * TT * DD) / 4;  // 1,048,576 float4 units
    cvt_kernel<<<n4 / 256, 256>>>(lt, rt);

    cudaFuncSetAttribute(match_kernel,
                         cudaFuncAttributeMaxDynamicSharedMemorySize, S_TOTAL);
    dim3 grid(TT / TM, MPP / NM, BB);  // (2, 4, 32) = 256 CTAs
    match_kernel<<<grid, 256, S_TOTAL>>>(kw, out);
}